// round 1
// baseline (speedup 1.0000x reference)
#include <cuda_runtime.h>
#include <math.h>

#define BB 8
#define SS 2048
#define EE 512
#define HD 64

// scratch q/k/v buffers (allocation-free rule: use __device__ globals)
__device__ float g_q[BB*SS*HD];
__device__ float g_k[BB*SS*HD];
__device__ float g_v[BB*SS*HD];

// ---------------------------------------------------------------------------
// Kernel 1: fused QKV projection. One kernel, blockIdx.y selects Wq/Wk/Wv.
// C[M=16384, N=64] = X[M,512] @ W[512,64].  BM=128, BK=16, 256 thr, 8x4 micro.
// ---------------------------------------------------------------------------
#define QKV_BM 128
#define QKV_BK 16

__global__ __launch_bounds__(256) void qkv_kernel(
    const float* __restrict__ x,
    const float* __restrict__ Wq,
    const float* __restrict__ Wk,
    const float* __restrict__ Wv)
{
    __shared__ float Xts[QKV_BK][QKV_BM + 4];   // transposed: [k][m]
    __shared__ float Wsm[QKV_BK][HD];           // natural:    [k][n]

    const int which = blockIdx.y;
    const float* W  = (which == 0) ? Wq : ((which == 1) ? Wk : Wv);
    float* outp     = (which == 0) ? g_q : ((which == 1) ? g_k : g_v);

    const int tid = threadIdx.x;
    const int ty  = tid >> 4;     // 0..15 -> 8 rows each
    const int tx  = tid & 15;     // 0..15 -> 4 cols each
    const int rowBase = blockIdx.x * QKV_BM;

    float acc[8][4];
    #pragma unroll
    for (int i = 0; i < 8; i++)
        #pragma unroll
        for (int j = 0; j < 4; j++) acc[i][j] = 0.f;

    for (int kb = 0; kb < EE; kb += QKV_BK) {
        // load X tile (128x16) transposed into smem
        #pragma unroll
        for (int l = 0; l < 2; l++) {
            int idx = tid + l * 256;
            int r   = idx >> 2;          // 0..127
            int kq  = (idx & 3) * 4;     // 0,4,8,12
            float4 f = *(const float4*)&x[(size_t)(rowBase + r) * EE + kb + kq];
            Xts[kq + 0][r] = f.x;
            Xts[kq + 1][r] = f.y;
            Xts[kq + 2][r] = f.z;
            Xts[kq + 3][r] = f.w;
        }
        // load W tile (16x64) natural
        {
            int k = tid >> 4;
            int c = (tid & 15) * 4;
            *(float4*)&Wsm[k][c] = *(const float4*)&W[(size_t)(kb + k) * HD + c];
        }
        __syncthreads();

        #pragma unroll
        for (int k = 0; k < QKV_BK; k++) {
            float a[8], bv[4];
            *(float4*)&a[0] = *(const float4*)&Xts[k][ty * 8];
            *(float4*)&a[4] = *(const float4*)&Xts[k][ty * 8 + 4];
            *(float4*)&bv[0] = *(const float4*)&Wsm[k][tx * 4];
            #pragma unroll
            for (int i = 0; i < 8; i++)
                #pragma unroll
                for (int j = 0; j < 4; j++)
                    acc[i][j] = fmaf(a[i], bv[j], acc[i][j]);
        }
        __syncthreads();
    }

    #pragma unroll
    for (int i = 0; i < 8; i++) {
        float4 f;
        f.x = acc[i][0]; f.y = acc[i][1]; f.z = acc[i][2]; f.w = acc[i][3];
        *(float4*)&outp[(size_t)(rowBase + ty * 8 + i) * HD + tx * 4] = f;
    }
}

// ---------------------------------------------------------------------------
// Kernel 2: flash attention, 64 queries x 64 keys per block, 256 threads,
// 4x4 register micro-tiles. Q and K stored transposed in smem so the S GEMM
// inner loop is 2x LDS.128 per 16 FFMA, conflict-free. P reuses K's smem.
// ---------------------------------------------------------------------------
#define PADK 68

__global__ __launch_bounds__(256) void attn_kernel(
    const int* __restrict__ mask, float* __restrict__ out)
{
    extern __shared__ float sm[];
    float* Qts = sm;                      // [64][64]   (d-major: [kk][row])
    float* Kts = sm + 64 * 64;            // [64][PADK] ([kk][col]), reused as Pt [kc][row]
    float* Vs  = Kts + 64 * PADK;         // [64][PADK] ([krow][d])
    int*   maskS = (int*)(Vs + 64 * PADK);

    const int b   = blockIdx.y;
    const int qt  = gridDim.x - 1 - blockIdx.x;   // heavy (large qt) blocks first
    const int tid = threadIdx.x;
    const int ty  = tid >> 4;   // 0..15 -> 4 query rows each
    const int tx  = tid & 15;   // 0..15 -> 4 cols each

    // load Q tile (64x64) transposed
    const float* qp = g_q + ((size_t)b * SS + (size_t)qt * 64) * HD;
    #pragma unroll
    for (int l = 0; l < 4; l++) {
        int idx = tid + l * 256;
        int r   = idx >> 4;          // 0..63
        int dq  = (idx & 15) * 4;    // 0..60
        float4 f = *(const float4*)&qp[r * HD + dq];
        Qts[(dq + 0) * 64 + r] = f.x;
        Qts[(dq + 1) * 64 + r] = f.y;
        Qts[(dq + 2) * 64 + r] = f.z;
        Qts[(dq + 3) * 64 + r] = f.w;
    }

    float m_i[4], l_i[4], o[4][4];
    #pragma unroll
    for (int i = 0; i < 4; i++) {
        m_i[i] = -1e30f; l_i[i] = 0.f;
        #pragma unroll
        for (int j = 0; j < 4; j++) o[i][j] = 0.f;
    }

    const int rowg0 = qt * 64 + ty * 4;

    for (int kt = 0; kt <= qt; kt++) {
        __syncthreads();   // protect Kts(/Pt)/Vs/maskS from previous iteration
        const float* kp = g_k + ((size_t)b * SS + (size_t)kt * 64) * HD;
        const float* vp = g_v + ((size_t)b * SS + (size_t)kt * 64) * HD;
        #pragma unroll
        for (int l = 0; l < 4; l++) {
            int idx = tid + l * 256;
            int r   = idx >> 4;
            int dq  = (idx & 15) * 4;
            float4 f = *(const float4*)&kp[r * HD + dq];
            Kts[(dq + 0) * PADK + r] = f.x;
            Kts[(dq + 1) * PADK + r] = f.y;
            Kts[(dq + 2) * PADK + r] = f.z;
            Kts[(dq + 3) * PADK + r] = f.w;
            float4 g = *(const float4*)&vp[r * HD + dq];
            *(float4*)&Vs[r * PADK + dq] = g;
        }
        if (tid < 64) maskS[tid] = mask[(size_t)b * SS + kt * 64 + tid];
        __syncthreads();

        // S = Q K^T for this 64x64 tile
        float s4[4][4];
        #pragma unroll
        for (int i = 0; i < 4; i++)
            #pragma unroll
            for (int j = 0; j < 4; j++) s4[i][j] = 0.f;

        #pragma unroll 16
        for (int kk = 0; kk < 64; kk++) {
            float4 q4 = *(const float4*)&Qts[kk * 64 + ty * 4];
            float4 k4 = *(const float4*)&Kts[kk * PADK + tx * 4];
            float qa[4] = {q4.x, q4.y, q4.z, q4.w};
            float ka[4] = {k4.x, k4.y, k4.z, k4.w};
            #pragma unroll
            for (int i = 0; i < 4; i++)
                #pragma unroll
                for (int j = 0; j < 4; j++)
                    s4[i][j] = fmaf(qa[i], ka[j], s4[i][j]);
        }

        const int colg0 = kt * 64 + tx * 4;
        int mk[4];
        #pragma unroll
        for (int j = 0; j < 4; j++) mk[j] = maskS[tx * 4 + j];

        __syncthreads();          // done reading Kts; reuse as Pt
        float* Pt = Kts;

        #pragma unroll
        for (int i = 0; i < 4; i++) {
            const int rowg = rowg0 + i;
            float v[4];
            #pragma unroll
            for (int j = 0; j < 4; j++) {
                bool keep = ((colg0 + j) <= rowg) && (mk[j] != 0);
                v[j] = keep ? s4[i][j] * 0.125f : -1e30f;   // scale = 64^-0.5
            }
            float mx = fmaxf(fmaxf(v[0], v[1]), fmaxf(v[2], v[3]));
            mx = fmaxf(mx, __shfl_xor_sync(0xffffffffu, mx, 1));
            mx = fmaxf(mx, __shfl_xor_sync(0xffffffffu, mx, 2));
            mx = fmaxf(mx, __shfl_xor_sync(0xffffffffu, mx, 4));
            mx = fmaxf(mx, __shfl_xor_sync(0xffffffffu, mx, 8));
            const float mnew = fmaxf(m_i[i], mx);
            float p[4];
            float sum = 0.f;
            #pragma unroll
            for (int j = 0; j < 4; j++) { p[j] = __expf(v[j] - mnew); sum += p[j]; }
            sum += __shfl_xor_sync(0xffffffffu, sum, 1);
            sum += __shfl_xor_sync(0xffffffffu, sum, 2);
            sum += __shfl_xor_sync(0xffffffffu, sum, 4);
            sum += __shfl_xor_sync(0xffffffffu, sum, 8);
            const float alpha = __expf(m_i[i] - mnew);
            m_i[i] = mnew;
            l_i[i] = l_i[i] * alpha + sum;
            #pragma unroll
            for (int j = 0; j < 4; j++) {
                o[i][j] *= alpha;
                Pt[(tx * 4 + j) * PADK + (ty * 4 + i)] = p[j];
            }
        }
        __syncthreads();

        // O += P @ V
        #pragma unroll 16
        for (int kc = 0; kc < 64; kc++) {
            float4 p4 = *(const float4*)&Pt[kc * PADK + ty * 4];
            float4 v4 = *(const float4*)&Vs[kc * PADK + tx * 4];
            float pa[4] = {p4.x, p4.y, p4.z, p4.w};
            float va[4] = {v4.x, v4.y, v4.z, v4.w};
            #pragma unroll
            for (int i = 0; i < 4; i++)
                #pragma unroll
                for (int j = 0; j < 4; j++)
                    o[i][j] = fmaf(pa[i], va[j], o[i][j]);
        }
    }

    #pragma unroll
    for (int i = 0; i < 4; i++) {
        const float inv = (l_i[i] > 0.f) ? 1.0f / l_i[i] : 0.f;
        float4 f;
        f.x = o[i][0] * inv; f.y = o[i][1] * inv;
        f.z = o[i][2] * inv; f.w = o[i][3] * inv;
        *(float4*)&out[((size_t)b * SS + (size_t)qt * 64 + ty * 4 + i) * HD + tx * 4] = f;
    }
}

// ---------------------------------------------------------------------------
extern "C" void kernel_launch(void* const* d_in, const int* in_sizes, int n_in,
                              void* d_out, int out_size)
{
    const float* x    = (const float*)d_in[0];
    const float* Wq   = (const float*)d_in[1];
    const float* Wk   = (const float*)d_in[2];
    const float* Wv   = (const float*)d_in[3];
    const int*   mask = (const int*)d_in[4];
    float* out = (float*)d_out;

    dim3 g1(BB * SS / QKV_BM, 3);
    qkv_kernel<<<g1, 256>>>(x, Wq, Wk, Wv);

    const int smbytes = 64 * 64 * 4 + 2 * 64 * PADK * 4 + 64 * 4;  // 51456
    cudaFuncSetAttribute(attn_kernel,
                         cudaFuncAttributeMaxDynamicSharedMemorySize, smbytes);
    dim3 g2(SS / 64, BB);
    attn_kernel<<<g2, 256, smbytes>>>(mask, out);
}

// round 3
// speedup vs baseline: 1.7841x; 1.7841x over previous
#include <cuda_runtime.h>
#include <cuda_bf16.h>
#include <cstdint>

#define BB 8
#define SS 2048
#define EE 512
#define HD 64

// scratch buffers (allocation-free rule: __device__ globals)
__device__ float g_q[BB*SS*HD];
__device__ float g_k[BB*SS*HD];
__device__ float g_v[BB*SS*HD];
// split-KV partial results: 2 splits
__device__ float g_po[2*BB*SS*HD];
__device__ float g_pm[2*BB*SS];
__device__ float g_pl[2*BB*SS];

// ---------------------------------------------------------------------------
// helpers: smem addr, ldmatrix, mma.sync bf16 (sm_80-baseline PTX, OK on sm_103)
// ---------------------------------------------------------------------------
__device__ __forceinline__ uint32_t smem_to_u32(const void* p) {
    uint32_t a;
    asm("{ .reg .u64 t; cvta.to.shared.u64 t, %1; cvt.u32.u64 %0, t; }"
        : "=r"(a) : "l"(p));
    return a;
}
__device__ __forceinline__ void ldmatrix_x4(
    uint32_t& r0, uint32_t& r1, uint32_t& r2, uint32_t& r3, uint32_t addr)
{
    asm volatile("ldmatrix.sync.aligned.m8n8.x4.shared.b16 {%0,%1,%2,%3}, [%4];"
        : "=r"(r0), "=r"(r1), "=r"(r2), "=r"(r3) : "r"(addr));
}
__device__ __forceinline__ void mma16816(
    float* c, const uint32_t* a, uint32_t b0, uint32_t b1)
{
    asm volatile(
        "mma.sync.aligned.m16n8k16.row.col.f32.bf16.bf16.f32 "
        "{%0,%1,%2,%3}, {%4,%5,%6,%7}, {%8,%9}, {%0,%1,%2,%3};"
        : "+f"(c[0]), "+f"(c[1]), "+f"(c[2]), "+f"(c[3])
        : "r"(a[0]), "r"(a[1]), "r"(a[2]), "r"(a[3]), "r"(b0), "r"(b1));
}

// ---------------------------------------------------------------------------
// Kernel 1: fused QKV via HMMA bf16 hi/lo (3-MMA fp32 emulation).
// CTA = 128 rows x 64 cols x 3 outputs; 8 warps (4 along M, 2 along N).
// K=512 in 8 chunks of 64. smem XOR-swizzled for conflict-free ldmatrix/LDS.
// ---------------------------------------------------------------------------
#define SM_A_HI 0
#define SM_A_LO 16384
#define SM_B_OFF(w, hl) (32768 + (w) * 16384 + (hl) * 8192)
#define QKV_SMEM (32768 + 3 * 16384)   // 81920 bytes

__global__ __launch_bounds__(256, 1) void qkv_tc_kernel(
    const float* __restrict__ x,
    const float* __restrict__ Wq,
    const float* __restrict__ Wk,
    const float* __restrict__ Wv)
{
    extern __shared__ char smem[];
    const uint32_t smem_base = smem_to_u32(smem);
    const int tid = threadIdx.x;
    const int wid = tid >> 5;
    const int lid = tid & 31;
    const int warpM = wid & 3;        // 4 warps along M (32 rows each)
    const int warpN = wid >> 2;       // 2 warps along N (32 cols each)
    const float* Ws[3] = {Wq, Wk, Wv};
    float* outs[3] = {g_q, g_k, g_v};

    const int rowBase = blockIdx.x * 128;

    float acc[3][2][4][4];
    #pragma unroll
    for (int w = 0; w < 3; w++)
        #pragma unroll
        for (int mt = 0; mt < 2; mt++)
            #pragma unroll
            for (int nt = 0; nt < 4; nt++)
                #pragma unroll
                for (int e = 0; e < 4; e++) acc[w][mt][nt][e] = 0.f;

    for (int kb = 0; kb < EE; kb += 64) {
        __syncthreads();   // previous iteration's consumers done

        // ---- produce A chunk: x[rowBase..+128][kb..+64] -> bf16 hi/lo ----
        #pragma unroll
        for (int l = 0; l < 8; l++) {
            int idx = tid + l * 256;          // 0..2047
            int r   = idx >> 4;               // 0..127
            int c   = (idx & 15) * 4;         // 0..60
            float4 f = *(const float4*)&x[(size_t)(rowBase + r) * EE + kb + c];
            __nv_bfloat16 h0 = __float2bfloat16(f.x);
            __nv_bfloat16 h1 = __float2bfloat16(f.y);
            __nv_bfloat16 h2 = __float2bfloat16(f.z);
            __nv_bfloat16 h3 = __float2bfloat16(f.w);
            __nv_bfloat16 l0 = __float2bfloat16(f.x - __bfloat162float(h0));
            __nv_bfloat16 l1 = __float2bfloat16(f.y - __bfloat162float(h1));
            __nv_bfloat16 l2 = __float2bfloat16(f.z - __bfloat162float(h2));
            __nv_bfloat16 l3 = __float2bfloat16(f.w - __bfloat162float(h3));
            uint32_t xr = (uint32_t)((r & 7) << 4);
            uint32_t o0 = (uint32_t)(r * 128) + (((uint32_t)(2 * c)) ^ xr);
            uint32_t o1 = (uint32_t)(r * 128) + (((uint32_t)(2 * (c + 2))) ^ xr);
            *(__nv_bfloat162*)(smem + SM_A_HI + o0) = __nv_bfloat162{h0, h1};
            *(__nv_bfloat162*)(smem + SM_A_HI + o1) = __nv_bfloat162{h2, h3};
            *(__nv_bfloat162*)(smem + SM_A_LO + o0) = __nv_bfloat162{l0, l1};
            *(__nv_bfloat162*)(smem + SM_A_LO + o1) = __nv_bfloat162{l2, l3};
        }
        // ---- produce B chunks: W[kb+k][n] -> [n][k] bf16 hi/lo, 3 mats ----
        {
            const int n   = tid & 63;
            const int seg = tid >> 6;         // 0..3, each covers 16 k
            #pragma unroll
            for (int w = 0; w < 3; w++) {
                const float* Wp = Ws[w];
                #pragma unroll
                for (int kk = 0; kk < 16; kk += 2) {
                    int k = seg * 16 + kk;
                    float f0 = Wp[(size_t)(kb + k)     * HD + n];
                    float f1 = Wp[(size_t)(kb + k + 1) * HD + n];
                    __nv_bfloat16 h0 = __float2bfloat16(f0);
                    __nv_bfloat16 h1 = __float2bfloat16(f1);
                    __nv_bfloat16 q0 = __float2bfloat16(f0 - __bfloat162float(h0));
                    __nv_bfloat16 q1 = __float2bfloat16(f1 - __bfloat162float(h1));
                    uint32_t off = (uint32_t)(n * 128) +
                                   (((uint32_t)(2 * k)) ^ ((uint32_t)((n & 7) << 4)));
                    *(__nv_bfloat162*)(smem + SM_B_OFF(w, 0) + off) = __nv_bfloat162{h0, h1};
                    *(__nv_bfloat162*)(smem + SM_B_OFF(w, 1) + off) = __nv_bfloat162{q0, q1};
                }
            }
        }
        __syncthreads();

        // ---- consume: 4 k-steps of 16 ----
        #pragma unroll
        for (int ks = 0; ks < 4; ks++) {
            const int k0 = ks * 16;
            uint32_t ah[2][4], al[2][4];
            #pragma unroll
            for (int mt = 0; mt < 2; mt++) {
                int mi  = lid >> 3;
                int row = warpM * 32 + mt * 16 + ((mi & 1) << 3) + (lid & 7);
                int kk  = k0 + ((mi >> 1) << 3);
                uint32_t off = (uint32_t)(row * 128) +
                               (((uint32_t)(2 * kk)) ^ ((uint32_t)((row & 7) << 4)));
                ldmatrix_x4(ah[mt][0], ah[mt][1], ah[mt][2], ah[mt][3],
                            smem_base + SM_A_HI + off);
                ldmatrix_x4(al[mt][0], al[mt][1], al[mt][2], al[mt][3],
                            smem_base + SM_A_LO + off);
            }
            #pragma unroll
            for (int w = 0; w < 3; w++) {
                #pragma unroll
                for (int nt = 0; nt < 4; nt++) {
                    int c     = warpN * 32 + nt * 8 + (lid >> 2);
                    int kbase = k0 + (lid & 3) * 2;
                    uint32_t xr = (uint32_t)((c & 7) << 4);
                    uint32_t o0 = (uint32_t)(c * 128) + (((uint32_t)(2 * kbase)) ^ xr);
                    uint32_t o1 = (uint32_t)(c * 128) + (((uint32_t)(2 * (kbase + 8))) ^ xr);
                    uint32_t bh0 = *(const uint32_t*)(smem + SM_B_OFF(w, 0) + o0);
                    uint32_t bh1 = *(const uint32_t*)(smem + SM_B_OFF(w, 0) + o1);
                    uint32_t bl0 = *(const uint32_t*)(smem + SM_B_OFF(w, 1) + o0);
                    uint32_t bl1 = *(const uint32_t*)(smem + SM_B_OFF(w, 1) + o1);
                    #pragma unroll
                    for (int mt = 0; mt < 2; mt++) {
                        mma16816(acc[w][mt][nt], ah[mt], bh0, bh1);
                        mma16816(acc[w][mt][nt], ah[mt], bl0, bl1);
                        mma16816(acc[w][mt][nt], al[mt], bh0, bh1);
                    }
                }
            }
        }
    }

    // ---- epilogue ----
    #pragma unroll
    for (int w = 0; w < 3; w++) {
        float* op = outs[w];
        #pragma unroll
        for (int mt = 0; mt < 2; mt++) {
            int r0 = rowBase + warpM * 32 + mt * 16 + (lid >> 2);
            #pragma unroll
            for (int nt = 0; nt < 4; nt++) {
                int c = warpN * 32 + nt * 8 + (lid & 3) * 2;
                *(float2*)&op[(size_t)r0 * HD + c] =
                    make_float2(acc[w][mt][nt][0], acc[w][mt][nt][1]);
                *(float2*)&op[(size_t)(r0 + 8) * HD + c] =
                    make_float2(acc[w][mt][nt][2], acc[w][mt][nt][3]);
            }
        }
    }
}

// ---------------------------------------------------------------------------
// Kernel 2: flash attention, split-KV x2 (blockIdx.z), partial (m,l,O) out.
// ---------------------------------------------------------------------------
#define PADK 68

__global__ __launch_bounds__(256) void attn_kernel(const int* __restrict__ mask)
{
    extern __shared__ float sm[];
    float* Qts = sm;                      // [64][64]   (d-major)
    float* Kts = sm + 64 * 64;            // [64][PADK], reused as Pt
    float* Vs  = Kts + 64 * PADK;         // [64][PADK]
    int*   maskS = (int*)(Vs + 64 * PADK);

    const int b   = blockIdx.y;
    const int qt  = gridDim.x - 1 - blockIdx.x;   // heavy blocks first
    const int s   = blockIdx.z;                   // split 0/1
    const int tid = threadIdx.x;
    const int ty  = tid >> 4;
    const int tx  = tid & 15;

    const float* qp = g_q + ((size_t)b * SS + (size_t)qt * 64) * HD;
    #pragma unroll
    for (int l = 0; l < 4; l++) {
        int idx = tid + l * 256;
        int r   = idx >> 4;
        int dq  = (idx & 15) * 4;
        float4 f = *(const float4*)&qp[r * HD + dq];
        Qts[(dq + 0) * 64 + r] = f.x;
        Qts[(dq + 1) * 64 + r] = f.y;
        Qts[(dq + 2) * 64 + r] = f.z;
        Qts[(dq + 3) * 64 + r] = f.w;
    }

    float m_i[4], l_i[4], o[4][4];
    #pragma unroll
    for (int i = 0; i < 4; i++) {
        m_i[i] = -1e30f; l_i[i] = 0.f;
        #pragma unroll
        for (int j = 0; j < 4; j++) o[i][j] = 0.f;
    }

    const int rowg0 = qt * 64 + ty * 4;

    for (int kt = s; kt <= qt; kt += 2) {
        __syncthreads();
        const float* kp = g_k + ((size_t)b * SS + (size_t)kt * 64) * HD;
        const float* vp = g_v + ((size_t)b * SS + (size_t)kt * 64) * HD;
        #pragma unroll
        for (int l = 0; l < 4; l++) {
            int idx = tid + l * 256;
            int r   = idx >> 4;
            int dq  = (idx & 15) * 4;
            float4 f = *(const float4*)&kp[r * HD + dq];
            Kts[(dq + 0) * PADK + r] = f.x;
            Kts[(dq + 1) * PADK + r] = f.y;
            Kts[(dq + 2) * PADK + r] = f.z;
            Kts[(dq + 3) * PADK + r] = f.w;
            float4 g = *(const float4*)&vp[r * HD + dq];
            *(float4*)&Vs[r * PADK + dq] = g;
        }
        if (tid < 64) maskS[tid] = mask[(size_t)b * SS + kt * 64 + tid];
        __syncthreads();

        float s4[4][4];
        #pragma unroll
        for (int i = 0; i < 4; i++)
            #pragma unroll
            for (int j = 0; j < 4; j++) s4[i][j] = 0.f;

        #pragma unroll 16
        for (int kk = 0; kk < 64; kk++) {
            float4 q4 = *(const float4*)&Qts[kk * 64 + ty * 4];
            float4 k4 = *(const float4*)&Kts[kk * PADK + tx * 4];
            float qa[4] = {q4.x, q4.y, q4.z, q4.w};
            float ka[4] = {k4.x, k4.y, k4.z, k4.w};
            #pragma unroll
            for (int i = 0; i < 4; i++)
                #pragma unroll
                for (int j = 0; j < 4; j++)
                    s4[i][j] = fmaf(qa[i], ka[j], s4[i][j]);
        }

        const int colg0 = kt * 64 + tx * 4;
        int mk[4];
        #pragma unroll
        for (int j = 0; j < 4; j++) mk[j] = maskS[tx * 4 + j];

        __syncthreads();
        float* Pt = Kts;

        #pragma unroll
        for (int i = 0; i < 4; i++) {
            const int rowg = rowg0 + i;
            float v[4];
            #pragma unroll
            for (int j = 0; j < 4; j++) {
                bool keep = ((colg0 + j) <= rowg) && (mk[j] != 0);
                v[j] = keep ? s4[i][j] * 0.125f : -1e30f;
            }
            float mx = fmaxf(fmaxf(v[0], v[1]), fmaxf(v[2], v[3]));
            mx = fmaxf(mx, __shfl_xor_sync(0xffffffffu, mx, 1));
            mx = fmaxf(mx, __shfl_xor_sync(0xffffffffu, mx, 2));
            mx = fmaxf(mx, __shfl_xor_sync(0xffffffffu, mx, 4));
            mx = fmaxf(mx, __shfl_xor_sync(0xffffffffu, mx, 8));
            const float mnew = fmaxf(m_i[i], mx);
            float p[4];
            float sum = 0.f;
            #pragma unroll
            for (int j = 0; j < 4; j++) { p[j] = __expf(v[j] - mnew); sum += p[j]; }
            sum += __shfl_xor_sync(0xffffffffu, sum, 1);
            sum += __shfl_xor_sync(0xffffffffu, sum, 2);
            sum += __shfl_xor_sync(0xffffffffu, sum, 4);
            sum += __shfl_xor_sync(0xffffffffu, sum, 8);
            const float alpha = __expf(m_i[i] - mnew);
            m_i[i] = mnew;
            l_i[i] = l_i[i] * alpha + sum;
            #pragma unroll
            for (int j = 0; j < 4; j++) {
                o[i][j] *= alpha;
                Pt[(tx * 4 + j) * PADK + (ty * 4 + i)] = p[j];
            }
        }
        __syncthreads();

        #pragma unroll 16
        for (int kc = 0; kc < 64; kc++) {
            float4 p4 = *(const float4*)&Pt[kc * PADK + ty * 4];
            float4 v4 = *(const float4*)&Vs[kc * PADK + tx * 4];
            float pa[4] = {p4.x, p4.y, p4.z, p4.w};
            float va[4] = {v4.x, v4.y, v4.z, v4.w};
            #pragma unroll
            for (int i = 0; i < 4; i++)
                #pragma unroll
                for (int j = 0; j < 4; j++)
                    o[i][j] = fmaf(pa[i], va[j], o[i][j]);
        }
    }

    // write UNNORMALIZED partial O + (m, l) for this split
    float* po = g_po + (size_t)s * BB * SS * HD;
    #pragma unroll
    for (int i = 0; i < 4; i++) {
        size_t rowIdx = (size_t)b * SS + (size_t)qt * 64 + ty * 4 + i;
        float4 f;
        f.x = o[i][0]; f.y = o[i][1]; f.z = o[i][2]; f.w = o[i][3];
        *(float4*)&po[rowIdx * HD + tx * 4] = f;
        if (tx == 0) {
            g_pm[(size_t)s * BB * SS + rowIdx] = m_i[i];
            g_pl[(size_t)s * BB * SS + rowIdx] = l_i[i];
        }
    }
}

// ---------------------------------------------------------------------------
// Kernel 3: merge the two split-KV partials.
// ---------------------------------------------------------------------------
__global__ __launch_bounds__(256) void combine_kernel(float* __restrict__ out)
{
    int idx = blockIdx.x * 256 + threadIdx.x;   // over BB*SS*16
    int row = idx >> 4;
    int c   = (idx & 15) * 4;
    float m0 = g_pm[row],          l0 = g_pl[row];
    float m1 = g_pm[BB*SS + row],  l1 = g_pl[BB*SS + row];
    float m  = fmaxf(m0, m1);
    float w0 = __expf(m0 - m);
    float w1 = __expf(m1 - m);
    float denom = w0 * l0 + w1 * l1;
    float inv = (denom > 0.f) ? 1.0f / denom : 0.f;
    float4 a  = *(const float4*)&g_po[(size_t)row * HD + c];
    float4 bq = *(const float4*)&g_po[(size_t)BB * SS * HD + (size_t)row * HD + c];
    float4 r;
    r.x = (w0 * a.x + w1 * bq.x) * inv;
    r.y = (w0 * a.y + w1 * bq.y) * inv;
    r.z = (w0 * a.z + w1 * bq.z) * inv;
    r.w = (w0 * a.w + w1 * bq.w) * inv;
    *(float4*)&out[(size_t)row * HD + c] = r;
}

// ---------------------------------------------------------------------------
extern "C" void kernel_launch(void* const* d_in, const int* in_sizes, int n_in,
                              void* d_out, int out_size)
{
    const float* x    = (const float*)d_in[0];
    const float* Wq   = (const float*)d_in[1];
    const float* Wk   = (const float*)d_in[2];
    const float* Wv   = (const float*)d_in[3];
    const int*   mask = (const int*)d_in[4];
    float* out = (float*)d_out;

    cudaFuncSetAttribute(qkv_tc_kernel,
                         cudaFuncAttributeMaxDynamicSharedMemorySize, QKV_SMEM);
    qkv_tc_kernel<<<BB * SS / 128, 256, QKV_SMEM>>>(x, Wq, Wk, Wv);

    const int smbytes = 64 * 64 * 4 + 2 * 64 * PADK * 4 + 64 * 4;
    cudaFuncSetAttribute(attn_kernel,
                         cudaFuncAttributeMaxDynamicSharedMemorySize, smbytes);
    dim3 g2(SS / 64, BB, 2);
    attn_kernel<<<g2, 256, smbytes>>>(mask);

    combine_kernel<<<BB * SS * 16 / 256, 256>>>(out);
}

// round 4
// speedup vs baseline: 3.3936x; 1.9022x over previous
#include <cuda_runtime.h>
#include <cuda_bf16.h>
#include <cstdint>

#define BB 8
#define SS 2048
#define EE 512
#define HD 64

// scratch buffers (allocation-free rule: __device__ globals)
__device__ __nv_bfloat16 g_qh[BB*SS*HD];
__device__ __nv_bfloat16 g_ql[BB*SS*HD];
__device__ __nv_bfloat16 g_kh[BB*SS*HD];
__device__ __nv_bfloat16 g_kl[BB*SS*HD];
__device__ __nv_bfloat16 g_vh[BB*SS*HD];
__device__ __nv_bfloat16 g_vl[BB*SS*HD];
// split-KV partial results: 2 splits
__device__ float g_po[2*BB*SS*HD];
__device__ float g_pm[2*BB*SS];
__device__ float g_pl[2*BB*SS];

// ---------------------------------------------------------------------------
// helpers (sm_80-baseline PTX, compiles for plain sm_103)
// ---------------------------------------------------------------------------
__device__ __forceinline__ uint32_t smem_to_u32(const void* p) {
    uint32_t a;
    asm("{ .reg .u64 t; cvta.to.shared.u64 t, %1; cvt.u32.u64 %0, t; }"
        : "=r"(a) : "l"(p));
    return a;
}
__device__ __forceinline__ void ldmatrix_x4(
    uint32_t& r0, uint32_t& r1, uint32_t& r2, uint32_t& r3, uint32_t addr)
{
    asm volatile("ldmatrix.sync.aligned.m8n8.x4.shared.b16 {%0,%1,%2,%3}, [%4];"
        : "=r"(r0), "=r"(r1), "=r"(r2), "=r"(r3) : "r"(addr));
}
__device__ __forceinline__ void ldmatrix_x4_trans(
    uint32_t& r0, uint32_t& r1, uint32_t& r2, uint32_t& r3, uint32_t addr)
{
    asm volatile("ldmatrix.sync.aligned.m8n8.x4.trans.shared.b16 {%0,%1,%2,%3}, [%4];"
        : "=r"(r0), "=r"(r1), "=r"(r2), "=r"(r3) : "r"(addr));
}
__device__ __forceinline__ void mma16816(
    float* c, const uint32_t* a, uint32_t b0, uint32_t b1)
{
    asm volatile(
        "mma.sync.aligned.m16n8k16.row.col.f32.bf16.bf16.f32 "
        "{%0,%1,%2,%3}, {%4,%5,%6,%7}, {%8,%9}, {%0,%1,%2,%3};"
        : "+f"(c[0]), "+f"(c[1]), "+f"(c[2]), "+f"(c[3])
        : "r"(a[0]), "r"(a[1]), "r"(a[2]), "r"(a[3]), "r"(b0), "r"(b1));
}
__device__ __forceinline__ uint32_t pack2(__nv_bfloat16 a, __nv_bfloat16 b) {
    __nv_bfloat162 t; t.x = a; t.y = b;
    return *(uint32_t*)&t;
}

// ---------------------------------------------------------------------------
// Kernel 1: fused QKV via HMMA bf16 hi/lo; writes q/k/v as bf16 hi+lo arrays.
// CTA = 64 rows x 64 cols x 3 outputs; 8 warps (4 along M x 16 rows, 2 along N).
// ---------------------------------------------------------------------------
#define SM_A_HI 0
#define SM_A_LO 8192
#define SM_B_OFF(w, hl) (16384 + (w) * 16384 + (hl) * 8192)
#define QKV_SMEM (16384 + 3 * 16384)   // 65536 bytes

__global__ __launch_bounds__(256, 1) void qkv_tc_kernel(
    const float* __restrict__ x,
    const float* __restrict__ Wq,
    const float* __restrict__ Wk,
    const float* __restrict__ Wv)
{
    extern __shared__ char smem[];
    const uint32_t sb = smem_to_u32(smem);
    const int tid = threadIdx.x;
    const int wid = tid >> 5;
    const int lid = tid & 31;
    const int warpM = wid & 3;
    const int warpN = wid >> 2;
    const float* Ws[3] = {Wq, Wk, Wv};

    const int rowBase = blockIdx.x * 64;

    float acc[3][4][4];
    #pragma unroll
    for (int w = 0; w < 3; w++)
        #pragma unroll
        for (int nt = 0; nt < 4; nt++)
            #pragma unroll
            for (int e = 0; e < 4; e++) acc[w][nt][e] = 0.f;

    const int g = lid >> 3;
    const int rr = lid & 7;

    for (int kb = 0; kb < EE; kb += 64) {
        __syncthreads();
        // A tile 64x64 -> bf16 hi/lo, swizzled
        #pragma unroll
        for (int l = 0; l < 4; l++) {
            int idx = tid + l * 256;
            int r   = idx >> 4;
            int c   = (idx & 15) * 4;
            float4 f = *(const float4*)&x[(size_t)(rowBase + r) * EE + kb + c];
            __nv_bfloat16 h0 = __float2bfloat16(f.x);
            __nv_bfloat16 h1 = __float2bfloat16(f.y);
            __nv_bfloat16 h2 = __float2bfloat16(f.z);
            __nv_bfloat16 h3 = __float2bfloat16(f.w);
            __nv_bfloat16 l0 = __float2bfloat16(f.x - __bfloat162float(h0));
            __nv_bfloat16 l1 = __float2bfloat16(f.y - __bfloat162float(h1));
            __nv_bfloat16 l2 = __float2bfloat16(f.z - __bfloat162float(h2));
            __nv_bfloat16 l3 = __float2bfloat16(f.w - __bfloat162float(h3));
            uint32_t xr = (uint32_t)((r & 7) << 4);
            uint32_t o0 = (uint32_t)(r * 128) + (((uint32_t)(2 * c)) ^ xr);
            uint32_t o1 = (uint32_t)(r * 128) + (((uint32_t)(2 * (c + 2))) ^ xr);
            *(__nv_bfloat162*)(smem + SM_A_HI + o0) = __nv_bfloat162{h0, h1};
            *(__nv_bfloat162*)(smem + SM_A_HI + o1) = __nv_bfloat162{h2, h3};
            *(__nv_bfloat162*)(smem + SM_A_LO + o0) = __nv_bfloat162{l0, l1};
            *(__nv_bfloat162*)(smem + SM_A_LO + o1) = __nv_bfloat162{l2, l3};
        }
        // B tiles: W^T [n][k] hi/lo, 3 mats
        {
            const int n   = tid & 63;
            const int seg = tid >> 6;
            #pragma unroll
            for (int w = 0; w < 3; w++) {
                const float* Wp = Ws[w];
                #pragma unroll
                for (int kk = 0; kk < 16; kk += 2) {
                    int k = seg * 16 + kk;
                    float f0 = Wp[(size_t)(kb + k)     * HD + n];
                    float f1 = Wp[(size_t)(kb + k + 1) * HD + n];
                    __nv_bfloat16 h0 = __float2bfloat16(f0);
                    __nv_bfloat16 h1 = __float2bfloat16(f1);
                    __nv_bfloat16 q0 = __float2bfloat16(f0 - __bfloat162float(h0));
                    __nv_bfloat16 q1 = __float2bfloat16(f1 - __bfloat162float(h1));
                    uint32_t off = (uint32_t)(n * 128) +
                                   (((uint32_t)(2 * k)) ^ ((uint32_t)((n & 7) << 4)));
                    *(__nv_bfloat162*)(smem + SM_B_OFF(w, 0) + off) = __nv_bfloat162{h0, h1};
                    *(__nv_bfloat162*)(smem + SM_B_OFF(w, 1) + off) = __nv_bfloat162{q0, q1};
                }
            }
        }
        __syncthreads();

        #pragma unroll
        for (int ks = 0; ks < 4; ks++) {
            // A frags
            int arow = warpM * 16 + rr + ((g & 1) << 3);
            int ad   = ks * 16 + ((g >> 1) << 3);
            uint32_t aoff = (uint32_t)(arow * 128) +
                            (((uint32_t)(2 * ad)) ^ ((uint32_t)((arow & 7) << 4)));
            uint32_t ah[4], al[4];
            ldmatrix_x4(ah[0], ah[1], ah[2], ah[3], sb + SM_A_HI + aoff);
            ldmatrix_x4(al[0], al[1], al[2], al[3], sb + SM_A_LO + aoff);
            #pragma unroll
            for (int w = 0; w < 3; w++) {
                #pragma unroll
                for (int np = 0; np < 2; np++) {
                    int key = warpN * 32 + np * 16 + rr + ((g >> 1) << 3);
                    int d   = ks * 16 + ((g & 1) << 3);
                    uint32_t boff = (uint32_t)(key * 128) +
                                    (((uint32_t)(2 * d)) ^ ((uint32_t)((key & 7) << 4)));
                    uint32_t bh0, bh1, bh2, bh3, bl0, bl1, bl2, bl3;
                    ldmatrix_x4(bh0, bh1, bh2, bh3, sb + SM_B_OFF(w, 0) + boff);
                    ldmatrix_x4(bl0, bl1, bl2, bl3, sb + SM_B_OFF(w, 1) + boff);
                    mma16816(acc[w][2*np],   ah, bh0, bh1);
                    mma16816(acc[w][2*np],   ah, bl0, bl1);
                    mma16816(acc[w][2*np],   al, bh0, bh1);
                    mma16816(acc[w][2*np+1], ah, bh2, bh3);
                    mma16816(acc[w][2*np+1], ah, bl2, bl3);
                    mma16816(acc[w][2*np+1], al, bh2, bh3);
                }
            }
        }
    }

    // epilogue: write hi/lo bf16
    __nv_bfloat16* outsH[3] = {g_qh, g_kh, g_vh};
    __nv_bfloat16* outsL[3] = {g_ql, g_kl, g_vl};
    #pragma unroll
    for (int w = 0; w < 3; w++) {
        int r0 = rowBase + warpM * 16 + (lid >> 2);
        #pragma unroll
        for (int nt = 0; nt < 4; nt++) {
            int c = warpN * 32 + nt * 8 + (lid & 3) * 2;
            #pragma unroll
            for (int half = 0; half < 2; half++) {
                float v0 = acc[w][nt][half * 2 + 0];
                float v1 = acc[w][nt][half * 2 + 1];
                int row = r0 + half * 8;
                __nv_bfloat16 h0 = __float2bfloat16(v0);
                __nv_bfloat16 h1 = __float2bfloat16(v1);
                __nv_bfloat16 l0 = __float2bfloat16(v0 - __bfloat162float(h0));
                __nv_bfloat16 l1 = __float2bfloat16(v1 - __bfloat162float(h1));
                *(__nv_bfloat162*)&outsH[w][(size_t)row * HD + c] = __nv_bfloat162{h0, h1};
                *(__nv_bfloat162*)&outsL[w][(size_t)row * HD + c] = __nv_bfloat162{l0, l1};
            }
        }
    }
}

// ---------------------------------------------------------------------------
// Kernel 2: HMMA flash attention, 64 q / CTA, 4 warps (16 rows each),
// split-KV x2. Q/K/V bf16 hi/lo from gmem. S->P stays in registers.
// ---------------------------------------------------------------------------
#define A_KH 0
#define A_KL 8192
#define A_VH 16384
#define A_VL 24576
#define A_MASK 32768
#define ATT_SMEM (32768 + 256)

__global__ __launch_bounds__(128, 1) void attn_kernel(const int* __restrict__ mask)
{
    extern __shared__ char smem[];
    const uint32_t sb = smem_to_u32(smem);
    int* maskS = (int*)(smem + A_MASK);

    const int b     = blockIdx.y;
    const int qtile = gridDim.x - 1 - blockIdx.x;   // heavy first
    const int s     = blockIdx.z;
    const int tid   = threadIdx.x;
    const int wid   = tid >> 5;
    const int lid   = tid & 31;
    const int g     = lid >> 3;
    const int rr    = lid & 7;

    // ---- stage Q hi/lo into smem (reuse K area), then ldmatrix to regs ----
    {
        const __nv_bfloat16* qh = g_qh + ((size_t)b * SS + (size_t)qtile * 64) * HD;
        const __nv_bfloat16* ql = g_ql + ((size_t)b * SS + (size_t)qtile * 64) * HD;
        #pragma unroll
        for (int l = 0; l < 4; l++) {
            int idx = tid + l * 128;          // 0..511
            int r   = idx >> 3;               // 0..63
            int d0  = (idx & 7) * 8;          // 0..56
            uint32_t off = (uint32_t)(r * 128) +
                           (((uint32_t)(2 * d0)) ^ ((uint32_t)((r & 7) << 4)));
            *(float4*)(smem + A_KH + off) = *(const float4*)&qh[(size_t)r * HD + d0];
            *(float4*)(smem + A_KL + off) = *(const float4*)&ql[(size_t)r * HD + d0];
        }
    }
    __syncthreads();
    uint32_t qfh[4][4], qfl[4][4];
    #pragma unroll
    for (int ks = 0; ks < 4; ks++) {
        int row = wid * 16 + rr + ((g & 1) << 3);
        int d   = ks * 16 + ((g >> 1) << 3);
        uint32_t off = (uint32_t)(row * 128) +
                       (((uint32_t)(2 * d)) ^ ((uint32_t)((row & 7) << 4)));
        ldmatrix_x4(qfh[ks][0], qfh[ks][1], qfh[ks][2], qfh[ks][3], sb + A_KH + off);
        ldmatrix_x4(qfl[ks][0], qfl[ks][1], qfl[ks][2], qfl[ks][3], sb + A_KL + off);
    }

    float m0 = -1e30f, m1 = -1e30f, lsum0 = 0.f, lsum1 = 0.f;
    float oacc[8][4];
    #pragma unroll
    for (int nt = 0; nt < 8; nt++)
        #pragma unroll
        for (int e = 0; e < 4; e++) oacc[nt][e] = 0.f;

    const int qg0 = qtile * 64 + wid * 16 + (lid >> 2);
    const int qg1 = qg0 + 8;

    for (int kt = s; kt <= qtile; kt += 2) {
        __syncthreads();   // previous tile consumers done (also covers Q staging)
        {
            const size_t base = ((size_t)b * SS + (size_t)kt * 64) * HD;
            #pragma unroll
            for (int l = 0; l < 4; l++) {
                int idx = tid + l * 128;
                int r   = idx >> 3;
                int d0  = (idx & 7) * 8;
                uint32_t off = (uint32_t)(r * 128) +
                               (((uint32_t)(2 * d0)) ^ ((uint32_t)((r & 7) << 4)));
                size_t gi = base + (size_t)r * HD + d0;
                *(float4*)(smem + A_KH + off) = *(const float4*)&g_kh[gi];
                *(float4*)(smem + A_KL + off) = *(const float4*)&g_kl[gi];
                *(float4*)(smem + A_VH + off) = *(const float4*)&g_vh[gi];
                *(float4*)(smem + A_VL + off) = *(const float4*)&g_vl[gi];
            }
            if (tid < 64) maskS[tid] = mask[(size_t)b * SS + kt * 64 + tid];
        }
        __syncthreads();

        // ---- S = Q K^T (bf16 hi/lo, 3-term) ----
        float sacc[8][4];
        #pragma unroll
        for (int nt = 0; nt < 8; nt++)
            #pragma unroll
            for (int e = 0; e < 4; e++) sacc[nt][e] = 0.f;

        #pragma unroll
        for (int ks = 0; ks < 4; ks++) {
            #pragma unroll
            for (int np = 0; np < 4; np++) {
                int key = np * 16 + rr + ((g >> 1) << 3);
                int d   = ks * 16 + ((g & 1) << 3);
                uint32_t boff = (uint32_t)(key * 128) +
                                (((uint32_t)(2 * d)) ^ ((uint32_t)((key & 7) << 4)));
                uint32_t bh0, bh1, bh2, bh3, bl0, bl1, bl2, bl3;
                ldmatrix_x4(bh0, bh1, bh2, bh3, sb + A_KH + boff);
                ldmatrix_x4(bl0, bl1, bl2, bl3, sb + A_KL + boff);
                mma16816(sacc[2*np],   qfh[ks], bh0, bh1);
                mma16816(sacc[2*np],   qfh[ks], bl0, bl1);
                mma16816(sacc[2*np],   qfl[ks], bh0, bh1);
                mma16816(sacc[2*np+1], qfh[ks], bh2, bh3);
                mma16816(sacc[2*np+1], qfh[ks], bl2, bl3);
                mma16816(sacc[2*np+1], qfl[ks], bh2, bh3);
            }
        }

        // ---- mask + scale + online softmax ----
        float vmax0 = -1e30f, vmax1 = -1e30f;
        #pragma unroll
        for (int nt = 0; nt < 8; nt++) {
            int c0 = nt * 8 + (lid & 3) * 2;
            int kg0 = kt * 64 + c0;
            int mk0 = maskS[c0];
            int mk1 = maskS[c0 + 1];
            bool k00 = (kg0     <= qg0) && mk0;
            bool k01 = (kg0 + 1 <= qg0) && mk1;
            bool k10 = (kg0     <= qg1) && mk0;
            bool k11 = (kg0 + 1 <= qg1) && mk1;
            sacc[nt][0] = k00 ? sacc[nt][0] * 0.125f : -1e30f;
            sacc[nt][1] = k01 ? sacc[nt][1] * 0.125f : -1e30f;
            sacc[nt][2] = k10 ? sacc[nt][2] * 0.125f : -1e30f;
            sacc[nt][3] = k11 ? sacc[nt][3] * 0.125f : -1e30f;
            vmax0 = fmaxf(vmax0, fmaxf(sacc[nt][0], sacc[nt][1]));
            vmax1 = fmaxf(vmax1, fmaxf(sacc[nt][2], sacc[nt][3]));
        }
        vmax0 = fmaxf(vmax0, __shfl_xor_sync(0xffffffffu, vmax0, 1));
        vmax0 = fmaxf(vmax0, __shfl_xor_sync(0xffffffffu, vmax0, 2));
        vmax1 = fmaxf(vmax1, __shfl_xor_sync(0xffffffffu, vmax1, 1));
        vmax1 = fmaxf(vmax1, __shfl_xor_sync(0xffffffffu, vmax1, 2));
        float mn0 = fmaxf(m0, vmax0);
        float mn1 = fmaxf(m1, vmax1);
        float alpha0 = __expf(m0 - mn0);
        float alpha1 = __expf(m1 - mn1);
        float sum0 = 0.f, sum1 = 0.f;
        #pragma unroll
        for (int nt = 0; nt < 8; nt++) {
            sacc[nt][0] = __expf(sacc[nt][0] - mn0);
            sacc[nt][1] = __expf(sacc[nt][1] - mn0);
            sacc[nt][2] = __expf(sacc[nt][2] - mn1);
            sacc[nt][3] = __expf(sacc[nt][3] - mn1);
            sum0 += sacc[nt][0] + sacc[nt][1];
            sum1 += sacc[nt][2] + sacc[nt][3];
        }
        sum0 += __shfl_xor_sync(0xffffffffu, sum0, 1);
        sum0 += __shfl_xor_sync(0xffffffffu, sum0, 2);
        sum1 += __shfl_xor_sync(0xffffffffu, sum1, 1);
        sum1 += __shfl_xor_sync(0xffffffffu, sum1, 2);
        m0 = mn0; m1 = mn1;
        lsum0 = lsum0 * alpha0 + sum0;
        lsum1 = lsum1 * alpha1 + sum1;
        #pragma unroll
        for (int nt = 0; nt < 8; nt++) {
            oacc[nt][0] *= alpha0; oacc[nt][1] *= alpha0;
            oacc[nt][2] *= alpha1; oacc[nt][3] *= alpha1;
        }

        // ---- O += P V (P hi/lo from registers, V hi/lo via ldmatrix.trans) ----
        #pragma unroll
        for (int ks = 0; ks < 4; ks++) {
            uint32_t pah[4], pal[4];
            #pragma unroll
            for (int half = 0; half < 2; half++) {
                float v0 = sacc[2*ks + half][0], v1 = sacc[2*ks + half][1];
                float v2 = sacc[2*ks + half][2], v3 = sacc[2*ks + half][3];
                __nv_bfloat16 h0 = __float2bfloat16(v0);
                __nv_bfloat16 h1 = __float2bfloat16(v1);
                __nv_bfloat16 h2 = __float2bfloat16(v2);
                __nv_bfloat16 h3 = __float2bfloat16(v3);
                pah[half * 2 + 0] = pack2(h0, h1);
                pah[half * 2 + 1] = pack2(h2, h3);
                pal[half * 2 + 0] = pack2(__float2bfloat16(v0 - __bfloat162float(h0)),
                                          __float2bfloat16(v1 - __bfloat162float(h1)));
                pal[half * 2 + 1] = pack2(__float2bfloat16(v2 - __bfloat162float(h2)),
                                          __float2bfloat16(v3 - __bfloat162float(h3)));
            }
            // NOTE: fragment order fix — a0,a1 are rows/rows+8 of cols k0..k0+7
            // (sacc[2ks][0,1] rows lo, [2,3] rows hi); a2,a3 cols +8.
            uint32_t pa_h[4] = {pah[0], pah[1], pah[2], pah[3]};
            uint32_t pa_l[4] = {pal[0], pal[1], pal[2], pal[3]};
            #pragma unroll
            for (int np = 0; np < 4; np++) {
                int key = ks * 16 + rr + ((g & 1) << 3);
                int d   = np * 16 + ((g >> 1) << 3);
                uint32_t voff = (uint32_t)(key * 128) +
                                (((uint32_t)(2 * d)) ^ ((uint32_t)((key & 7) << 4)));
                uint32_t vh0, vh1, vh2, vh3, vl0, vl1, vl2, vl3;
                ldmatrix_x4_trans(vh0, vh1, vh2, vh3, sb + A_VH + voff);
                ldmatrix_x4_trans(vl0, vl1, vl2, vl3, sb + A_VL + voff);
                mma16816(oacc[2*np],   pa_h, vh0, vh1);
                mma16816(oacc[2*np],   pa_h, vl0, vl1);
                mma16816(oacc[2*np],   pa_l, vh0, vh1);
                mma16816(oacc[2*np+1], pa_h, vh2, vh3);
                mma16816(oacc[2*np+1], pa_h, vl2, vl3);
                mma16816(oacc[2*np+1], pa_l, vh2, vh3);
            }
        }
    }

    // ---- write unnormalized partial O + (m, l) ----
    float* po = g_po + (size_t)s * BB * SS * HD;
    size_t row0 = (size_t)b * SS + qg0 - 0;  // qg0 already global row
    size_t row1 = (size_t)b * SS + qg1;
    // careful: qg0 = qtile*64 + wid*16 + lid>>2 is the global q index within batch
    row0 = (size_t)b * SS + (size_t)(qtile * 64 + wid * 16 + (lid >> 2));
    #pragma unroll
    for (int nt = 0; nt < 8; nt++) {
        int c = nt * 8 + (lid & 3) * 2;
        *(float2*)&po[row0 * HD + c] = make_float2(oacc[nt][0], oacc[nt][1]);
        *(float2*)&po[row1 * HD + c] = make_float2(oacc[nt][2], oacc[nt][3]);
    }
    if ((lid & 3) == 0) {
        g_pm[(size_t)s * BB * SS + row0] = m0;
        g_pl[(size_t)s * BB * SS + row0] = lsum0;
        g_pm[(size_t)s * BB * SS + row1] = m1;
        g_pl[(size_t)s * BB * SS + row1] = lsum1;
    }
}

// ---------------------------------------------------------------------------
// Kernel 3: merge the two split-KV partials.
// ---------------------------------------------------------------------------
__global__ __launch_bounds__(256) void combine_kernel(float* __restrict__ out)
{
    int idx = blockIdx.x * 256 + threadIdx.x;   // over BB*SS*16
    int row = idx >> 4;
    int c   = (idx & 15) * 4;
    float m0 = g_pm[row],          l0 = g_pl[row];
    float m1 = g_pm[BB*SS + row],  l1 = g_pl[BB*SS + row];
    float m  = fmaxf(m0, m1);
    float w0 = __expf(m0 - m);
    float w1 = __expf(m1 - m);
    float denom = w0 * l0 + w1 * l1;
    float inv = (denom > 0.f) ? 1.0f / denom : 0.f;
    float4 a  = *(const float4*)&g_po[(size_t)row * HD + c];
    float4 bq = *(const float4*)&g_po[(size_t)BB * SS * HD + (size_t)row * HD + c];
    float4 r;
    r.x = (w0 * a.x + w1 * bq.x) * inv;
    r.y = (w0 * a.y + w1 * bq.y) * inv;
    r.z = (w0 * a.z + w1 * bq.z) * inv;
    r.w = (w0 * a.w + w1 * bq.w) * inv;
    *(float4*)&out[(size_t)row * HD + c] = r;
}

// ---------------------------------------------------------------------------
extern "C" void kernel_launch(void* const* d_in, const int* in_sizes, int n_in,
                              void* d_out, int out_size)
{
    const float* x    = (const float*)d_in[0];
    const float* Wq   = (const float*)d_in[1];
    const float* Wk   = (const float*)d_in[2];
    const float* Wv   = (const float*)d_in[3];
    const int*   mask = (const int*)d_in[4];
    float* out = (float*)d_out;

    cudaFuncSetAttribute(qkv_tc_kernel,
                         cudaFuncAttributeMaxDynamicSharedMemorySize, QKV_SMEM);
    qkv_tc_kernel<<<BB * SS / 64, 256, QKV_SMEM>>>(x, Wq, Wk, Wv);

    cudaFuncSetAttribute(attn_kernel,
                         cudaFuncAttributeMaxDynamicSharedMemorySize, ATT_SMEM);
    dim3 g2(SS / 64, BB, 2);
    attn_kernel<<<g2, 128, ATT_SMEM>>>(mask);

    combine_kernel<<<BB * SS * 16 / 256, 256>>>(out);
}

// round 5
// speedup vs baseline: 3.7363x; 1.1010x over previous
#include <cuda_runtime.h>
#include <cuda_bf16.h>
#include <cstdint>

#define BB 8
#define SS 2048
#define EE 512
#define HD 64

// preconverted operands (allocation-free rule: __device__ globals)
__device__ __nv_bfloat16 g_xh[BB*SS*EE];
__device__ __nv_bfloat16 g_xl[BB*SS*EE];
__device__ __nv_bfloat16 g_wt[6*HD*EE];   // [m=w*2+hl][n=64][k=512]
// q/k/v bf16 hi/lo
__device__ __nv_bfloat16 g_qh[BB*SS*HD];
__device__ __nv_bfloat16 g_ql[BB*SS*HD];
__device__ __nv_bfloat16 g_kh[BB*SS*HD];
__device__ __nv_bfloat16 g_kl[BB*SS*HD];
__device__ __nv_bfloat16 g_vh[BB*SS*HD];
__device__ __nv_bfloat16 g_vl[BB*SS*HD];
// split-KV partial results: 2 splits
__device__ float g_po[2*BB*SS*HD];
__device__ float g_pm[2*BB*SS];
__device__ float g_pl[2*BB*SS];

// ---------------------------------------------------------------------------
// helpers (sm_80-baseline PTX, compiles for plain sm_103)
// ---------------------------------------------------------------------------
__device__ __forceinline__ uint32_t smem_to_u32(const void* p) {
    uint32_t a;
    asm("{ .reg .u64 t; cvta.to.shared.u64 t, %1; cvt.u32.u64 %0, t; }"
        : "=r"(a) : "l"(p));
    return a;
}
__device__ __forceinline__ void ldmatrix_x4(
    uint32_t& r0, uint32_t& r1, uint32_t& r2, uint32_t& r3, uint32_t addr)
{
    asm volatile("ldmatrix.sync.aligned.m8n8.x4.shared.b16 {%0,%1,%2,%3}, [%4];"
        : "=r"(r0), "=r"(r1), "=r"(r2), "=r"(r3) : "r"(addr));
}
__device__ __forceinline__ void ldmatrix_x4_trans(
    uint32_t& r0, uint32_t& r1, uint32_t& r2, uint32_t& r3, uint32_t addr)
{
    asm volatile("ldmatrix.sync.aligned.m8n8.x4.trans.shared.b16 {%0,%1,%2,%3}, [%4];"
        : "=r"(r0), "=r"(r1), "=r"(r2), "=r"(r3) : "r"(addr));
}
__device__ __forceinline__ void mma16816(
    float* c, const uint32_t* a, uint32_t b0, uint32_t b1)
{
    asm volatile(
        "mma.sync.aligned.m16n8k16.row.col.f32.bf16.bf16.f32 "
        "{%0,%1,%2,%3}, {%4,%5,%6,%7}, {%8,%9}, {%0,%1,%2,%3};"
        : "+f"(c[0]), "+f"(c[1]), "+f"(c[2]), "+f"(c[3])
        : "r"(a[0]), "r"(a[1]), "r"(a[2]), "r"(a[3]), "r"(b0), "r"(b1));
}
__device__ __forceinline__ uint32_t pack2(__nv_bfloat16 a, __nv_bfloat16 b) {
    __nv_bfloat162 t; t.x = a; t.y = b;
    return *(uint32_t*)&t;
}
#define CP_ASYNC16(dst, src) \
    asm volatile("cp.async.cg.shared.global [%0], [%1], 16;" :: "r"(dst), "l"(src))
#define CP_COMMIT() asm volatile("cp.async.commit_group;" ::: "memory")
#define CP_WAIT(n)  asm volatile("cp.async.wait_group %0;" :: "n"(n) : "memory")

// ---------------------------------------------------------------------------
// Kernel 0a: X -> bf16 hi/lo
// ---------------------------------------------------------------------------
__global__ __launch_bounds__(256) void conv_x_kernel(const float* __restrict__ x)
{
    size_t i = ((size_t)blockIdx.x * 256 + threadIdx.x) * 4;
    float4 f = *(const float4*)&x[i];
    __nv_bfloat16 h0 = __float2bfloat16(f.x);
    __nv_bfloat16 h1 = __float2bfloat16(f.y);
    __nv_bfloat16 h2 = __float2bfloat16(f.z);
    __nv_bfloat16 h3 = __float2bfloat16(f.w);
    *(__nv_bfloat162*)&g_xh[i]     = __nv_bfloat162{h0, h1};
    *(__nv_bfloat162*)&g_xh[i + 2] = __nv_bfloat162{h2, h3};
    *(__nv_bfloat162*)&g_xl[i] = __nv_bfloat162{
        __float2bfloat16(f.x - __bfloat162float(h0)),
        __float2bfloat16(f.y - __bfloat162float(h1))};
    *(__nv_bfloat162*)&g_xl[i + 2] = __nv_bfloat162{
        __float2bfloat16(f.z - __bfloat162float(h2)),
        __float2bfloat16(f.w - __bfloat162float(h3))};
}

// ---------------------------------------------------------------------------
// Kernel 0b: W -> transposed bf16 hi/lo [m=w*2+hl][n][k]
// ---------------------------------------------------------------------------
__global__ __launch_bounds__(256) void conv_w_kernel(
    const float* __restrict__ Wq, const float* __restrict__ Wk,
    const float* __restrict__ Wv)
{
    int idx = blockIdx.x * 256 + threadIdx.x;    // < 6*64*512
    int m = idx >> 15;                // /(64*512)
    int n = (idx >> 9) & 63;
    int k = idx & 511;
    int w = m >> 1, hl = m & 1;
    const float* Wp = (w == 0) ? Wq : ((w == 1) ? Wk : Wv);
    float f = Wp[(size_t)k * HD + n];
    __nv_bfloat16 h = __float2bfloat16(f);
    g_wt[idx] = hl ? __float2bfloat16(f - __bfloat162float(h)) : h;
}

// ---------------------------------------------------------------------------
// Kernel 1: QKV GEMM, pure MMA + cp.async double-buffer.
// CTA = 64 rows; 8 warps (4 along M x 16 rows, 2 along N x 32 cols).
// smem per stage: A_HI 8K | A_LO 8K | B[m=0..5] 8K each  = 64KB; x2 stages.
// ---------------------------------------------------------------------------
#define QSTG 65536
#define QKV_SMEM (2 * QSTG)

__device__ __forceinline__ void qkv_load_stage(
    uint32_t sb, int stg, int rowBase, int kb, int tid)
{
    uint32_t base = sb + stg * QSTG;
    #pragma unroll
    for (int t = 0; t < 4; t++) {               // A hi (t<2) / lo
        int within = tid + (t & 1) * 256;       // 0..511
        int r = within >> 3, seg = within & 7;
        const __nv_bfloat16* src = (t < 2 ? g_xh : g_xl) +
            ((size_t)(rowBase + r) * EE + kb + seg * 8);
        uint32_t dst = base + (t < 2 ? 0 : 8192) +
            (uint32_t)(r * 128) + (((uint32_t)(seg * 16)) ^ ((uint32_t)((r & 7) << 4)));
        CP_ASYNC16(dst, src);
    }
    #pragma unroll
    for (int t = 0; t < 12; t++) {              // B mats m=t>>1
        const int m = t >> 1;
        int within = tid + (t & 1) * 256;
        int n = within >> 3, seg = within & 7;
        const __nv_bfloat16* src = g_wt + ((size_t)m * 64 + n) * EE + kb + seg * 8;
        uint32_t dst = base + 16384 + m * 8192 +
            (uint32_t)(n * 128) + (((uint32_t)(seg * 16)) ^ ((uint32_t)((n & 7) << 4)));
        CP_ASYNC16(dst, src);
    }
}

__global__ __launch_bounds__(256, 1) void qkv_tc_kernel()
{
    extern __shared__ char smem[];
    const uint32_t sb = smem_to_u32(smem);
    const int tid = threadIdx.x;
    const int wid = tid >> 5;
    const int lid = tid & 31;
    const int warpM = wid & 3;
    const int warpN = wid >> 2;
    const int rowBase = blockIdx.x * 64;
    const int g = lid >> 3;
    const int rr = lid & 7;

    float acc[3][4][4];
    #pragma unroll
    for (int w = 0; w < 3; w++)
        #pragma unroll
        for (int nt = 0; nt < 4; nt++)
            #pragma unroll
            for (int e = 0; e < 4; e++) acc[w][nt][e] = 0.f;

    qkv_load_stage(sb, 0, rowBase, 0, tid);
    CP_COMMIT();

    for (int c = 0; c < 8; c++) {
        if (c < 7) {
            qkv_load_stage(sb, (c + 1) & 1, rowBase, (c + 1) * 64, tid);
            CP_COMMIT();
            CP_WAIT(1);
        } else {
            CP_WAIT(0);
        }
        __syncthreads();

        const uint32_t stgb = sb + (c & 1) * QSTG;
        #pragma unroll
        for (int ks = 0; ks < 4; ks++) {
            int arow = warpM * 16 + rr + ((g & 1) << 3);
            int ad   = ks * 16 + ((g >> 1) << 3);
            uint32_t aoff = (uint32_t)(arow * 128) +
                            (((uint32_t)(2 * ad)) ^ ((uint32_t)((arow & 7) << 4)));
            uint32_t ah[4], al[4];
            ldmatrix_x4(ah[0], ah[1], ah[2], ah[3], stgb + aoff);
            ldmatrix_x4(al[0], al[1], al[2], al[3], stgb + 8192 + aoff);
            #pragma unroll
            for (int w = 0; w < 3; w++) {
                #pragma unroll
                for (int np = 0; np < 2; np++) {
                    int key = warpN * 32 + np * 16 + rr + ((g >> 1) << 3);
                    int d   = ks * 16 + ((g & 1) << 3);
                    uint32_t boff = (uint32_t)(key * 128) +
                                    (((uint32_t)(2 * d)) ^ ((uint32_t)((key & 7) << 4)));
                    uint32_t bh0, bh1, bh2, bh3, bl0, bl1, bl2, bl3;
                    ldmatrix_x4(bh0, bh1, bh2, bh3, stgb + 16384 + (w * 2) * 8192 + boff);
                    ldmatrix_x4(bl0, bl1, bl2, bl3, stgb + 16384 + (w * 2 + 1) * 8192 + boff);
                    mma16816(acc[w][2*np],   ah, bh0, bh1);
                    mma16816(acc[w][2*np],   ah, bl0, bl1);
                    mma16816(acc[w][2*np],   al, bh0, bh1);
                    mma16816(acc[w][2*np+1], ah, bh2, bh3);
                    mma16816(acc[w][2*np+1], ah, bl2, bl3);
                    mma16816(acc[w][2*np+1], al, bh2, bh3);
                }
            }
        }
        __syncthreads();
    }

    // epilogue: write hi/lo bf16
    __nv_bfloat16* outsH[3] = {g_qh, g_kh, g_vh};
    __nv_bfloat16* outsL[3] = {g_ql, g_kl, g_vl};
    #pragma unroll
    for (int w = 0; w < 3; w++) {
        int r0 = rowBase + warpM * 16 + (lid >> 2);
        #pragma unroll
        for (int nt = 0; nt < 4; nt++) {
            int c = warpN * 32 + nt * 8 + (lid & 3) * 2;
            #pragma unroll
            for (int half = 0; half < 2; half++) {
                float v0 = acc[w][nt][half * 2 + 0];
                float v1 = acc[w][nt][half * 2 + 1];
                int row = r0 + half * 8;
                __nv_bfloat16 h0 = __float2bfloat16(v0);
                __nv_bfloat16 h1 = __float2bfloat16(v1);
                __nv_bfloat16 l0 = __float2bfloat16(v0 - __bfloat162float(h0));
                __nv_bfloat16 l1 = __float2bfloat16(v1 - __bfloat162float(h1));
                *(__nv_bfloat162*)&outsH[w][(size_t)row * HD + c] = __nv_bfloat162{h0, h1};
                *(__nv_bfloat162*)&outsL[w][(size_t)row * HD + c] = __nv_bfloat162{l0, l1};
            }
        }
    }
}

// ---------------------------------------------------------------------------
// Kernel 2: HMMA flash attention, 64 q / CTA, 4 warps, split-KV x2,
// cp.async 2-stage K/V pipeline.  smem: Q 16K | 2 x (KH KL VH VL 8K each) | mask
// ---------------------------------------------------------------------------
#define A_STG0 16384
#define A_STGSZ 32768
#define A_MASK (16384 + 2 * A_STGSZ)   // 81920
#define ATT_SMEM (A_MASK + 512)

__device__ __forceinline__ void attn_load_stage(
    uint32_t sb, int stg, size_t base, const int* maskp, int tid)
{
    uint32_t sbase = sb + A_STG0 + stg * A_STGSZ;
    #pragma unroll
    for (int t = 0; t < 16; t++) {
        const int m = t >> 2;                 // 0=KH 1=KL 2=VH 3=VL
        int within = tid + (t & 3) * 128;     // 0..511
        int r = within >> 3, seg = within & 7;
        const __nv_bfloat16* srcb =
            (m == 0) ? g_kh : (m == 1) ? g_kl : (m == 2) ? g_vh : g_vl;
        const __nv_bfloat16* src = srcb + base + (size_t)r * HD + seg * 8;
        uint32_t dst = sbase + m * 8192 +
            (uint32_t)(r * 128) + (((uint32_t)(seg * 16)) ^ ((uint32_t)((r & 7) << 4)));
        CP_ASYNC16(dst, src);
    }
    if (tid < 16) CP_ASYNC16(sb + A_MASK + stg * 256 + tid * 16, maskp + tid * 4);
}

__global__ __launch_bounds__(128, 1) void attn_kernel(const int* __restrict__ mask)
{
    extern __shared__ char smem[];
    const uint32_t sb = smem_to_u32(smem);

    const int b     = blockIdx.y;
    const int qtile = gridDim.x - 1 - blockIdx.x;   // heavy first
    const int s     = blockIdx.z;
    const int tid   = threadIdx.x;
    const int wid   = tid >> 5;
    const int lid   = tid & 31;
    const int g     = lid >> 3;
    const int rr    = lid & 7;

    // stage Q hi/lo into its own smem region
    {
        const __nv_bfloat16* qh = g_qh + ((size_t)b * SS + (size_t)qtile * 64) * HD;
        const __nv_bfloat16* ql = g_ql + ((size_t)b * SS + (size_t)qtile * 64) * HD;
        #pragma unroll
        for (int l = 0; l < 4; l++) {
            int idx = tid + l * 128;
            int r   = idx >> 3;
            int d0  = (idx & 7) * 8;
            uint32_t off = (uint32_t)(r * 128) +
                           (((uint32_t)(2 * d0)) ^ ((uint32_t)((r & 7) << 4)));
            *(float4*)(smem + off)        = *(const float4*)&qh[(size_t)r * HD + d0];
            *(float4*)(smem + 8192 + off) = *(const float4*)&ql[(size_t)r * HD + d0];
        }
    }
    // prefetch first tile
    if (s <= qtile) {
        attn_load_stage(sb, 0, ((size_t)b * SS + (size_t)s * 64) * HD,
                        mask + (size_t)b * SS + s * 64, tid);
        CP_COMMIT();
    }
    __syncthreads();

    uint32_t qfh[4][4], qfl[4][4];
    #pragma unroll
    for (int ks = 0; ks < 4; ks++) {
        int row = wid * 16 + rr + ((g & 1) << 3);
        int d   = ks * 16 + ((g >> 1) << 3);
        uint32_t off = (uint32_t)(row * 128) +
                       (((uint32_t)(2 * d)) ^ ((uint32_t)((row & 7) << 4)));
        ldmatrix_x4(qfh[ks][0], qfh[ks][1], qfh[ks][2], qfh[ks][3], sb + off);
        ldmatrix_x4(qfl[ks][0], qfl[ks][1], qfl[ks][2], qfl[ks][3], sb + 8192 + off);
    }

    float m0 = -1e30f, m1 = -1e30f, lsum0 = 0.f, lsum1 = 0.f;
    float oacc[8][4];
    #pragma unroll
    for (int nt = 0; nt < 8; nt++)
        #pragma unroll
        for (int e = 0; e < 4; e++) oacc[nt][e] = 0.f;

    const int qg0 = qtile * 64 + wid * 16 + (lid >> 2);
    const int qg1 = qg0 + 8;

    for (int kt = s; kt <= qtile; kt += 2) {
        const int stg = ((kt - s) >> 1) & 1;
        const int ktn = kt + 2;
        if (ktn <= qtile) {
            attn_load_stage(sb, stg ^ 1, ((size_t)b * SS + (size_t)ktn * 64) * HD,
                            mask + (size_t)b * SS + ktn * 64, tid);
            CP_COMMIT();
            CP_WAIT(1);
        } else {
            CP_WAIT(0);
        }
        __syncthreads();

        const uint32_t kb = sb + A_STG0 + stg * A_STGSZ;
        const int* maskS = (const int*)(smem + A_MASK + stg * 256);

        // ---- S = Q K^T ----
        float sacc[8][4];
        #pragma unroll
        for (int nt = 0; nt < 8; nt++)
            #pragma unroll
            for (int e = 0; e < 4; e++) sacc[nt][e] = 0.f;

        #pragma unroll
        for (int ks = 0; ks < 4; ks++) {
            #pragma unroll
            for (int np = 0; np < 4; np++) {
                int key = np * 16 + rr + ((g >> 1) << 3);
                int d   = ks * 16 + ((g & 1) << 3);
                uint32_t boff = (uint32_t)(key * 128) +
                                (((uint32_t)(2 * d)) ^ ((uint32_t)((key & 7) << 4)));
                uint32_t bh0, bh1, bh2, bh3, bl0, bl1, bl2, bl3;
                ldmatrix_x4(bh0, bh1, bh2, bh3, kb + boff);
                ldmatrix_x4(bl0, bl1, bl2, bl3, kb + 8192 + boff);
                mma16816(sacc[2*np],   qfh[ks], bh0, bh1);
                mma16816(sacc[2*np],   qfh[ks], bl0, bl1);
                mma16816(sacc[2*np],   qfl[ks], bh0, bh1);
                mma16816(sacc[2*np+1], qfh[ks], bh2, bh3);
                mma16816(sacc[2*np+1], qfh[ks], bl2, bl3);
                mma16816(sacc[2*np+1], qfl[ks], bh2, bh3);
            }
        }

        // ---- mask + scale + online softmax ----
        float vmax0 = -1e30f, vmax1 = -1e30f;
        #pragma unroll
        for (int nt = 0; nt < 8; nt++) {
            int c0 = nt * 8 + (lid & 3) * 2;
            int kg0 = kt * 64 + c0;
            int mk0 = maskS[c0];
            int mk1 = maskS[c0 + 1];
            bool k00 = (kg0     <= qg0) && mk0;
            bool k01 = (kg0 + 1 <= qg0) && mk1;
            bool k10 = (kg0     <= qg1) && mk0;
            bool k11 = (kg0 + 1 <= qg1) && mk1;
            sacc[nt][0] = k00 ? sacc[nt][0] * 0.125f : -1e30f;
            sacc[nt][1] = k01 ? sacc[nt][1] * 0.125f : -1e30f;
            sacc[nt][2] = k10 ? sacc[nt][2] * 0.125f : -1e30f;
            sacc[nt][3] = k11 ? sacc[nt][3] * 0.125f : -1e30f;
            vmax0 = fmaxf(vmax0, fmaxf(sacc[nt][0], sacc[nt][1]));
            vmax1 = fmaxf(vmax1, fmaxf(sacc[nt][2], sacc[nt][3]));
        }
        vmax0 = fmaxf(vmax0, __shfl_xor_sync(0xffffffffu, vmax0, 1));
        vmax0 = fmaxf(vmax0, __shfl_xor_sync(0xffffffffu, vmax0, 2));
        vmax1 = fmaxf(vmax1, __shfl_xor_sync(0xffffffffu, vmax1, 1));
        vmax1 = fmaxf(vmax1, __shfl_xor_sync(0xffffffffu, vmax1, 2));
        float mn0 = fmaxf(m0, vmax0);
        float mn1 = fmaxf(m1, vmax1);
        float alpha0 = __expf(m0 - mn0);
        float alpha1 = __expf(m1 - mn1);
        float sum0 = 0.f, sum1 = 0.f;
        #pragma unroll
        for (int nt = 0; nt < 8; nt++) {
            sacc[nt][0] = __expf(sacc[nt][0] - mn0);
            sacc[nt][1] = __expf(sacc[nt][1] - mn0);
            sacc[nt][2] = __expf(sacc[nt][2] - mn1);
            sacc[nt][3] = __expf(sacc[nt][3] - mn1);
            sum0 += sacc[nt][0] + sacc[nt][1];
            sum1 += sacc[nt][2] + sacc[nt][3];
        }
        sum0 += __shfl_xor_sync(0xffffffffu, sum0, 1);
        sum0 += __shfl_xor_sync(0xffffffffu, sum0, 2);
        sum1 += __shfl_xor_sync(0xffffffffu, sum1, 1);
        sum1 += __shfl_xor_sync(0xffffffffu, sum1, 2);
        m0 = mn0; m1 = mn1;
        lsum0 = lsum0 * alpha0 + sum0;
        lsum1 = lsum1 * alpha1 + sum1;
        #pragma unroll
        for (int nt = 0; nt < 8; nt++) {
            oacc[nt][0] *= alpha0; oacc[nt][1] *= alpha0;
            oacc[nt][2] *= alpha1; oacc[nt][3] *= alpha1;
        }

        // ---- O += P V ----
        #pragma unroll
        for (int ks = 0; ks < 4; ks++) {
            uint32_t pa_h[4], pa_l[4];
            #pragma unroll
            for (int half = 0; half < 2; half++) {
                float v0 = sacc[2*ks + half][0], v1 = sacc[2*ks + half][1];
                float v2 = sacc[2*ks + half][2], v3 = sacc[2*ks + half][3];
                __nv_bfloat16 h0 = __float2bfloat16(v0);
                __nv_bfloat16 h1 = __float2bfloat16(v1);
                __nv_bfloat16 h2 = __float2bfloat16(v2);
                __nv_bfloat16 h3 = __float2bfloat16(v3);
                pa_h[half * 2 + 0] = pack2(h0, h1);
                pa_h[half * 2 + 1] = pack2(h2, h3);
                pa_l[half * 2 + 0] = pack2(__float2bfloat16(v0 - __bfloat162float(h0)),
                                           __float2bfloat16(v1 - __bfloat162float(h1)));
                pa_l[half * 2 + 1] = pack2(__float2bfloat16(v2 - __bfloat162float(h2)),
                                           __float2bfloat16(v3 - __bfloat162float(h3)));
            }
            #pragma unroll
            for (int np = 0; np < 4; np++) {
                int key = ks * 16 + rr + ((g & 1) << 3);
                int d   = np * 16 + ((g >> 1) << 3);
                uint32_t voff = (uint32_t)(key * 128) +
                                (((uint32_t)(2 * d)) ^ ((uint32_t)((key & 7) << 4)));
                uint32_t vh0, vh1, vh2, vh3, vl0, vl1, vl2, vl3;
                ldmatrix_x4_trans(vh0, vh1, vh2, vh3, kb + 16384 + voff);
                ldmatrix_x4_trans(vl0, vl1, vl2, vl3, kb + 24576 + voff);
                mma16816(oacc[2*np],   pa_h, vh0, vh1);
                mma16816(oacc[2*np],   pa_h, vl0, vl1);
                mma16816(oacc[2*np],   pa_l, vh0, vh1);
                mma16816(oacc[2*np+1], pa_h, vh2, vh3);
                mma16816(oacc[2*np+1], pa_h, vl2, vl3);
                mma16816(oacc[2*np+1], pa_l, vh2, vh3);
            }
        }
        __syncthreads();
    }

    // ---- write unnormalized partial O + (m, l) ----
    float* po = g_po + (size_t)s * BB * SS * HD;
    size_t row0 = (size_t)b * SS + (size_t)(qtile * 64 + wid * 16 + (lid >> 2));
    size_t row1 = row0 + 8;
    #pragma unroll
    for (int nt = 0; nt < 8; nt++) {
        int c = nt * 8 + (lid & 3) * 2;
        *(float2*)&po[row0 * HD + c] = make_float2(oacc[nt][0], oacc[nt][1]);
        *(float2*)&po[row1 * HD + c] = make_float2(oacc[nt][2], oacc[nt][3]);
    }
    if ((lid & 3) == 0) {
        g_pm[(size_t)s * BB * SS + row0] = m0;
        g_pl[(size_t)s * BB * SS + row0] = lsum0;
        g_pm[(size_t)s * BB * SS + row1] = m1;
        g_pl[(size_t)s * BB * SS + row1] = lsum1;
    }
}

// ---------------------------------------------------------------------------
// Kernel 3: merge the two split-KV partials.
// ---------------------------------------------------------------------------
__global__ __launch_bounds__(256) void combine_kernel(float* __restrict__ out)
{
    int idx = blockIdx.x * 256 + threadIdx.x;   // over BB*SS*16
    int row = idx >> 4;
    int c   = (idx & 15) * 4;
    float m0 = g_pm[row],          l0 = g_pl[row];
    float m1 = g_pm[BB*SS + row],  l1 = g_pl[BB*SS + row];
    float m  = fmaxf(m0, m1);
    float w0 = __expf(m0 - m);
    float w1 = __expf(m1 - m);
    float denom = w0 * l0 + w1 * l1;
    float inv = (denom > 0.f) ? 1.0f / denom : 0.f;
    float4 a  = *(const float4*)&g_po[(size_t)row * HD + c];
    float4 bq = *(const float4*)&g_po[(size_t)BB * SS * HD + (size_t)row * HD + c];
    float4 r;
    r.x = (w0 * a.x + w1 * bq.x) * inv;
    r.y = (w0 * a.y + w1 * bq.y) * inv;
    r.z = (w0 * a.z + w1 * bq.z) * inv;
    r.w = (w0 * a.w + w1 * bq.w) * inv;
    *(float4*)&out[(size_t)row * HD + c] = r;
}

// ---------------------------------------------------------------------------
extern "C" void kernel_launch(void* const* d_in, const int* in_sizes, int n_in,
                              void* d_out, int out_size)
{
    const float* x    = (const float*)d_in[0];
    const float* Wq   = (const float*)d_in[1];
    const float* Wk   = (const float*)d_in[2];
    const float* Wv   = (const float*)d_in[3];
    const int*   mask = (const int*)d_in[4];
    float* out = (float*)d_out;

    conv_w_kernel<<<6 * HD * EE / 256, 256>>>(Wq, Wk, Wv);
    conv_x_kernel<<<BB * SS * EE / 4 / 256, 256>>>(x);

    cudaFuncSetAttribute(qkv_tc_kernel,
                         cudaFuncAttributeMaxDynamicSharedMemorySize, QKV_SMEM);
    qkv_tc_kernel<<<BB * SS / 64, 256, QKV_SMEM>>>();

    cudaFuncSetAttribute(attn_kernel,
                         cudaFuncAttributeMaxDynamicSharedMemorySize, ATT_SMEM);
    dim3 g2(SS / 64, BB, 2);
    attn_kernel<<<g2, 128, ATT_SMEM>>>(mask);

    combine_kernel<<<BB * SS * 16 / 256, 256>>>(out);
}